// round 15
// baseline (speedup 1.0000x reference)
#include <cuda_runtime.h>
#include <cuda_bf16.h>
#include <cstdint>

#define CC 256
#define HH 128
#define WW 128
#define HWSZ (HH*WW)
#define WKP_W 132                  // wk pitch in words (264 bf16)
#define XBP2  72                   // per-group xbw pitch in words (64 gpix + 8 pad)
#define GBUF  (32*XBP2)            // words per group buffer = 2304

// shared layout in 4-byte units
#define SM_WK   0                          // [64][132] words = 8448
#define SM_XBW  8448                       // 2 groups x 2304 words = 4608
#define SMEM_WORDS (SM_XBW + 2*GBUF)       // 13056
#define SMEM_BYTES (SMEM_WORDS*4)          // 52224

// pre-converted, pre-padded bf16 w_key image [64][132] words
__device__ unsigned g_wkb[64*WKP_W];

__device__ __forceinline__ unsigned pack_bf2(float lo, float hi) {
    __nv_bfloat162 h = __floats2bfloat162_rn(lo, hi);
    return *reinterpret_cast<unsigned*>(&h);
}

#define PACK2(o, lo, hi) asm("mov.b64 %0, {%1, %2};" : "=l"(o) : "f"(lo), "f"(hi))
#define UNPACK2(lo, hi, i) asm("mov.b64 {%0, %1}, %2;" : "=f"(lo), "=f"(hi) : "l"(i))
#define FMA2(o, a, b) asm("fma.rn.f32x2 %0, %1, %2, %0;" : "+l"(o) : "l"(a), "l"(b))
#define NBAR(g) asm volatile("bar.sync %0, %1;" :: "r"((g) + 1), "r"(128) : "memory")

__global__ void prep_wkey(const float* __restrict__ w_key)
{
    int i = blockIdx.x*256 + threadIdx.x;
    if (i < 64*WKP_W) {
        int k = i / WKP_W, c2 = i % WKP_W;
        unsigned v = 0;
        if (c2 < 128) {
            float2 f = *(const float2*)(w_key + k*256 + c2*2);
            v = pack_bf2(f.x, f.y);
        }
        g_wkb[i] = v;
    }
}

__global__ __launch_bounds__(256, 4) void frac_fused_kernel(
    const float* __restrict__ x,
    const float* __restrict__ w_sim,
    float* __restrict__ out)
{
    extern __shared__ float S[];
    unsigned* wkw = (unsigned*)(S + SM_WK);         // [key][132] words, shared

    const int tid  = threadIdx.x;
    const int wp   = tid >> 5;         // 0..7
    const int lane = tid & 31;
    const int g    = wp >> 2;          // independent group 0/1 (cols 16g..16g+15)
    const int wg   = wp & 3;           // warp within group
    const int gt   = wg*32 + lane;     // thread within group [0,128)
    const int gid  = lane >> 2;        // 0..7
    const int ctid = lane & 3;         // 0..3
    const int grpM = wg & 1;           // 2 m-groups per group
    const int mtb  = grpM * 32;        // key rows mtb..mtb+31
    const int pixb = (wg >> 1) * 32;   // 2 pixel groups of 32 (of 64 gpix)
    const int wh = blockIdx.x;         // 0..3
    const int hh = blockIdx.y;         // 0..31
    const int n  = blockIdx.z;         // 0..15

    unsigned* xbw  = (unsigned*)(S + SM_XBW) + g*GBUF;  // [32 c2][72] words
    float*    kqs  = (float*)((unsigned*)(S + SM_XBW) + g*GBUF);  // alias post-GEMM
    float*    wbuf = kqs + 512;                          // alias: [4 win][68]

    const float* xpix = x + ((size_t)n*CC)*HWSZ + (size_t)(hh*4)*WW + wh*32;
    const float* xg   = xpix + 16*g;   // group's 16-column strip

    // ---- prologue: copy pre-converted bf16 w_key image into smem ----
    {
        const uint4* src = (const uint4*)g_wkb;
        uint4*       dst = (uint4*)wkw;
        for (int i = tid; i < (64*WKP_W)/4; i += 256) dst[i] = src[i];
    }
    // ---- convert chunk 0 into this group's xbw ----
    #pragma unroll
    for (int jj = 0; jj < 4; jj++) {
        int id = jj*128 + gt;              // 0..511 : c2l(32) x q(16)
        int c2l = id >> 4, q = id & 15;
        const float* p = xg + (size_t)(2*c2l)*HWSZ + (q >> 2)*WW + (q & 3)*4;
        float4 fa = *(const float4*)p;
        float4 fb = *(const float4*)(p + HWSZ);
        uint4 wv;
        wv.x = pack_bf2(fa.x, fb.x); wv.y = pack_bf2(fa.y, fb.y);
        wv.z = pack_bf2(fa.z, fb.z); wv.w = pack_bf2(fa.w, fb.w);
        *(uint4*)(xbw + c2l*XBP2 + q*4) = wv;
    }
    __syncthreads();                       // wk + both groups' chunk 0 visible

    // per-lane ldmatrix address for A (row = key, 16B col-half)
    const uint32_t wk_sb = (uint32_t)__cvta_generic_to_shared(S + SM_WK);
    const uint32_t a_lane_addr = wk_sb
        + (uint32_t)(((mtb + (lane & 15)) * (WKP_W*2) + (lane >> 4) * 8) * 2);

    float acc[2][4][4];
    #pragma unroll
    for (int t = 0; t < 2; t++)
        #pragma unroll
        for (int i = 0; i < 4; i++)
            #pragma unroll
            for (int j = 0; j < 4; j++) acc[t][i][j] = 0.f;

    #pragma unroll 1
    for (int ch = 0; ch < 4; ch++) {
        if (ch) {
            NBAR(g);                       // prev GEMM's B reads done (group only)
            #pragma unroll
            for (int jj = 0; jj < 4; jj++) {
                int id = jj*128 + gt;
                int c2l = id >> 4, q = id & 15;
                const float* p = xg + (size_t)(64*ch + 2*c2l)*HWSZ + (q >> 2)*WW + (q & 3)*4;
                float4 fa = *(const float4*)p;
                float4 fb = *(const float4*)(p + HWSZ);
                uint4 wv;
                wv.x = pack_bf2(fa.x, fb.x); wv.y = pack_bf2(fa.y, fb.y);
                wv.z = pack_bf2(fa.z, fb.z); wv.w = pack_bf2(fa.w, fb.w);
                *(uint4*)(xbw + c2l*XBP2 + q*4) = wv;
            }
            NBAR(g);                       // xbw ready (group only)
        }

        // ---- GEMM: 4 k16 slabs; warp tile M=32, gpix=32; B hoisted across t ----
        #pragma unroll
        for (int ktl = 0; ktl < 4; ktl++) {
            unsigned b[4][2];
            const int b0row = (ktl*8 + ctid)     * XBP2;
            const int b1row = (ktl*8 + ctid + 4) * XBP2;
            #pragma unroll
            for (int nt = 0; nt < 4; nt++) {
                int pix = pixb + nt*8 + gid;
                b[nt][0] = xbw[b0row + pix];
                b[nt][1] = xbw[b1row + pix];
            }
            #pragma unroll
            for (int t = 0; t < 2; t++) {
                unsigned a0, a1, a2, a3;
                asm volatile(
                    "ldmatrix.sync.aligned.m8n8.x4.shared.b16 {%0,%1,%2,%3}, [%4];"
                    : "=r"(a0), "=r"(a1), "=r"(a2), "=r"(a3)
                    : "r"(a_lane_addr + (unsigned)(t*16*WKP_W*4) + (unsigned)((ch*4 + ktl)*32)));
                #pragma unroll
                for (int nt = 0; nt < 4; nt++) {
                    asm volatile(
                        "mma.sync.aligned.m16n8k16.row.col.f32.bf16.bf16.f32 "
                        "{%0,%1,%2,%3}, {%4,%5,%6,%7}, {%8,%9}, {%0,%1,%2,%3};"
                        : "+f"(acc[t][nt][0]), "+f"(acc[t][nt][1]),
                          "+f"(acc[t][nt][2]), "+f"(acc[t][nt][3])
                        : "r"(a0), "r"(a1), "r"(a2), "r"(a3),
                          "r"(b[nt][0]), "r"(b[nt][1]));
                }
            }
        }
    }
    NBAR(g);                               // group's B reads done; region reusable as kqs

    // ---- epilogue kq: relu + w_sim contraction from accumulators ----
    float ws[4][4];
    #pragma unroll
    for (int s = 0; s < 4; s++) {
        ws[0][s] = w_sim[s*64 + mtb + gid];
        ws[1][s] = w_sim[s*64 + mtb + gid + 8];
        ws[2][s] = w_sim[s*64 + mtb + gid + 16];
        ws[3][s] = w_sim[s*64 + mtb + gid + 24];
    }
    #pragma unroll
    for (int nt = 0; nt < 4; nt++) {
        float part[2][4];
        #pragma unroll
        for (int u = 0; u < 2; u++) {
            float v0 = fmaxf(acc[0][nt][u],     0.f);
            float v1 = fmaxf(acc[0][nt][2 + u], 0.f);
            float v2 = fmaxf(acc[1][nt][u],     0.f);
            float v3 = fmaxf(acc[1][nt][2 + u], 0.f);
            #pragma unroll
            for (int s = 0; s < 4; s++)
                part[u][s] = ws[0][s]*v0 + ws[1][s]*v1 + ws[2][s]*v2 + ws[3][s]*v3;
        }
        #pragma unroll
        for (int off = 4; off <= 16; off <<= 1)
            #pragma unroll
            for (int u = 0; u < 2; u++)
                #pragma unroll
                for (int s = 0; s < 4; s++)
                    part[u][s] += __shfl_xor_sync(0xffffffffu, part[u][s], off);
        if (gid == 0) {
            #pragma unroll
            for (int u = 0; u < 2; u++) {
                int gpix = pixb + nt*8 + 2*ctid + u;      // gpix = r*16 + col
                *(float4*)(kqs + grpM*256 + gpix*4) = make_float4(
                    part[u][0], part[u][1], part[u][2], part[u][3]);
            }
        }
    }
    NBAR(g);                               // kqs complete

    // ---- per-window softmax (4 windows x 4 s = 16 threads of the group) ----
    if (gt < 16) {
        int win = gt >> 2, s = gt & 3;
        float v[16], m = -1e30f;
        #pragma unroll
        for (int r0 = 0; r0 < 4; r0++)
            #pragma unroll
            for (int j = 0; j < 4; j++) {
                int gpix = r0*16 + win*4 + j;
                float t = (kqs[gpix*4 + s] + kqs[256 + gpix*4 + s]) * 0.25f;
                v[r0*4+j] = t;
                m = fmaxf(m, t);
            }
        float sum = 0.f;
        #pragma unroll
        for (int p = 0; p < 16; p++) { float e = __expf(v[p]-m); v[p] = e; sum += e; }
        float inv = 1.f / sum;
        #pragma unroll
        for (int p = 0; p < 16; p++) wbuf[win*68 + p*4 + s] = v[p]*inv;
    }
    NBAR(g);                               // wbuf ready

    // ---- aggregation: thread = (win, c-slot); all 4 outputs per window ----
    {
        const int win   = gt & 3;
        const int cslot = gt >> 2;         // 0..31
        const int ww    = wh*8 + g*4 + win;
        unsigned long long o01[8], o23[8];
        #pragma unroll
        for (int it = 0; it < 8; it++) { o01[it] = 0ull; o23[it] = 0ull; }

        #pragma unroll
        for (int r0 = 0; r0 < 4; r0++) {
            unsigned long long w01[4], w23[4];
            #pragma unroll
            for (int j = 0; j < 4; j++) {
                float4 wv = *(const float4*)(wbuf + win*68 + (r0*4 + j)*4);
                PACK2(w01[j], wv.x, wv.y);
                PACK2(w23[j], wv.z, wv.w);
            }
            #pragma unroll
            for (int it = 0; it < 8; it++) {
                int c = it*32 + cslot;
                float4 xv = *(const float4*)(xg + (size_t)c*HWSZ + r0*WW + win*4);
                unsigned long long xp;
                PACK2(xp, xv.x, xv.x); FMA2(o01[it], xp, w01[0]); FMA2(o23[it], xp, w23[0]);
                PACK2(xp, xv.y, xv.y); FMA2(o01[it], xp, w01[1]); FMA2(o23[it], xp, w23[1]);
                PACK2(xp, xv.z, xv.z); FMA2(o01[it], xp, w01[2]); FMA2(o23[it], xp, w23[2]);
                PACK2(xp, xv.w, xv.w); FMA2(o01[it], xp, w01[3]); FMA2(o23[it], xp, w23[3]);
            }
        }
        #pragma unroll
        for (int it = 0; it < 8; it++) {
            int c = it*32 + cslot;
            float a0, a1;
            float* obase = out + ((size_t)(n*CC + c)*64 + 2*hh)*64 + 2*ww;
            UNPACK2(a0, a1, o01[it]);
            *(float2*)obase = make_float2(a0, a1);
            UNPACK2(a0, a1, o23[it]);
            *(float2*)(obase + 64) = make_float2(a0, a1);
        }
    }
}

extern "C" void kernel_launch(void* const* d_in, const int* in_sizes, int n_in,
                              void* d_out, int out_size)
{
    (void)in_sizes; (void)n_in; (void)out_size;
    const float* x  = (const float*)d_in[0];
    const float* wk = (const float*)d_in[1];
    const float* ws = (const float*)d_in[2];
    float* out = (float*)d_out;

    prep_wkey<<<(64*WKP_W + 255)/256, 256>>>(wk);
    cudaFuncSetAttribute(frac_fused_kernel,
                         cudaFuncAttributeMaxDynamicSharedMemorySize, SMEM_BYTES);
    frac_fused_kernel<<<dim3(4, 32, 16), 256, SMEM_BYTES>>>(x, ws, out);
}